// round 2
// baseline (speedup 1.0000x reference)
#include <cuda_runtime.h>

#define N_ANCH 5000
#define N_CLS 80
#define WORDS 157          // ceil(5000/32)
#define WSTRIDE 160        // padded row stride (640B)
#define MAXB 300
#define SCORE_THR_F 0.05f
#define OUT_COLS 84
#define NBUCK 4096
#define KEYCAP 5120

// symmetric suppression bitmask: bit j of word w of row i <=> iou(i,32w+j)>0.5 && i!=j
__device__ unsigned int g_mask[N_ANCH * WSTRIDE];
__device__ unsigned int g_kept[N_CLS * WSTRIDE];

// ---------------------------------------------------------------------------
// Kernel A: IoU>0.5 bitmask. 4 rows per warp. Division eliminated except in a
// 1e-6 relative band around the 0.5 boundary (exact __fdiv_rn fallback there),
// so the decision bit is identical to the reference's fl(inter/uni) > 0.5.
// ---------------------------------------------------------------------------
__global__ void __launch_bounds__(256)
iou_mask_kernel(const float4* __restrict__ boxes) {
    int warp = (blockIdx.x * blockDim.x + threadIdx.x) >> 5;
    int lane = threadIdx.x & 31;
    if (warp >= N_ANCH / 4) return;
    int r0 = warp * 4;

    float4 bi[4];
    float ai[4];
#pragma unroll
    for (int k = 0; k < 4; ++k) {
        bi[k] = __ldg(&boxes[r0 + k]);
        ai[k] = __fmul_rn(__fsub_rn(bi[k].z, bi[k].x), __fsub_rn(bi[k].w, bi[k].y));
    }

    for (int w = 0; w < WORDS; ++w) {
        int j = (w << 5) + lane;
        bool in = (j < N_ANCH);
        float4 bj = __ldg(&boxes[in ? j : 0]);
        float aj = __fmul_rn(__fsub_rn(bj.z, bj.x), __fsub_rn(bj.w, bj.y));

        unsigned int m[4];
#pragma unroll
        for (int k = 0; k < 4; ++k) {
            float iw = fmaxf(__fsub_rn(fminf(bi[k].z, bj.z), fmaxf(bi[k].x, bj.x)), 0.0f);
            float ih = fmaxf(__fsub_rn(fminf(bi[k].w, bj.w), fmaxf(bi[k].y, bj.y)), 0.0f);
            float inter = __fmul_rn(iw, ih);
            float uni = __fsub_rn(__fadd_rn(ai[k], aj), inter);  // >= 1 (areas >= 1)
            float diff = __fsub_rn(__fadd_rn(inter, inter), uni); // 2*inter exact
            bool pred = diff > 0.0f;
            if (fabsf(diff) <= __fmul_rn(uni, 1e-6f)) {           // ~never taken
                float iou = __fdiv_rn(inter, fmaxf(uni, 1e-8f));
                pred = (iou > 0.5f);
            }
            pred = pred && in && (j != r0 + k);
            m[k] = __ballot_sync(0xffffffffu, pred);
        }
        if (lane < 4)
            g_mask[(r0 + lane) * WSTRIDE + w] = m[lane];
    }
}

// ---------------------------------------------------------------------------
// Kernel B: one block (1024 thr) per class.
//   1) bucket counting-sort (4096 score buckets) + per-bucket insertion sort
//      of full (score_bits<<32 | ~idx) keys  -> exact stable descending order
//   2) warp-0 greedy scan: per 32-window, preload pairwise suppression bits
//      with independent LDGs, greedy on registers, batch-OR kept rows.
// ---------------------------------------------------------------------------
#define BT 1024

__global__ void __launch_bounds__(BT, 1)
nms_class_kernel(const float* __restrict__ cls) {
    extern __shared__ unsigned char sh_raw[];
    unsigned long long* keys = (unsigned long long*)sh_raw;          // KEYCAP u64
    unsigned int* hist   = (unsigned int*)(keys + KEYCAP);           // NBUCK
    unsigned int* starts = hist + NBUCK;                             // NBUCK
    __shared__ unsigned int supp[WSTRIDE];
    __shared__ unsigned int kept[WSTRIDE];
    __shared__ unsigned int klist[32];
    __shared__ unsigned int widx[32];
    __shared__ unsigned int wsum[32];
    __shared__ int s_cnt;

    const int c = blockIdx.x;
    const int tid = threadIdx.x;
    const int lane = tid & 31;
    const int wid = tid >> 5;

    for (int b = tid; b < NBUCK; b += BT) hist[b] = 0u;
    for (int w = tid; w < WSTRIDE; w += BT) { supp[w] = 0u; kept[w] = 0u; }
    __syncthreads();

    // histogram
    for (int i = tid; i < N_ANCH; i += BT) {
        float s = cls[i * N_CLS + c];
        if (s > SCORE_THR_F) {
            int b = min((int)__fmul_rn(s, 4096.0f), NBUCK - 1);
            atomicAdd(&hist[NBUCK - 1 - b], 1u);
        }
    }
    __syncthreads();

    // block exclusive scan over NBUCK bins (4 bins/thread)
    {
        unsigned int h0 = hist[tid * 4 + 0], h1 = hist[tid * 4 + 1];
        unsigned int h2 = hist[tid * 4 + 2], h3 = hist[tid * 4 + 3];
        unsigned int tsum = h0 + h1 + h2 + h3;
        unsigned int x = tsum;
#pragma unroll
        for (int o = 1; o < 32; o <<= 1) {
            unsigned int y = __shfl_up_sync(0xffffffffu, x, o);
            if (lane >= o) x += y;
        }
        if (lane == 31) wsum[wid] = x;
        __syncthreads();
        if (wid == 0) {
            unsigned int v = wsum[lane];
            unsigned int xx = v;
#pragma unroll
            for (int o = 1; o < 32; o <<= 1) {
                unsigned int y = __shfl_up_sync(0xffffffffu, xx, o);
                if (lane >= o) xx += y;
            }
            wsum[lane] = xx;                 // inclusive warp totals
            if (lane == 31) s_cnt = (int)xx; // total count
        }
        __syncthreads();
        unsigned int warp_excl = (wid > 0) ? wsum[wid - 1] : 0u;
        unsigned int te = warp_excl + (x - tsum);
        hist[tid * 4 + 0] = te;             starts[tid * 4 + 0] = te;
        hist[tid * 4 + 1] = te + h0;        starts[tid * 4 + 1] = te + h0;
        hist[tid * 4 + 2] = te + h0 + h1;   starts[tid * 4 + 2] = te + h0 + h1;
        hist[tid * 4 + 3] = te + h0 + h1 + h2; starts[tid * 4 + 3] = te + h0 + h1 + h2;
    }
    __syncthreads();
    const int cnt = s_cnt;

    // scatter
    for (int i = tid; i < N_ANCH; i += BT) {
        float s = cls[i * N_CLS + c];
        if (s > SCORE_THR_F) {
            int b = min((int)__fmul_rn(s, 4096.0f), NBUCK - 1);
            unsigned int pos = atomicAdd(&hist[NBUCK - 1 - b], 1u);
            keys[pos] = ((unsigned long long)__float_as_uint(s) << 32) |
                        (unsigned long long)(0xFFFFFFFFu - (unsigned int)i);
        }
    }
    __syncthreads();

    // per-bucket insertion sort (descending) -> exact stable order
    for (int b = tid; b < NBUCK; b += BT) {
        int s0 = (int)starts[b], e0 = (int)hist[b];
        for (int i = s0 + 1; i < e0; ++i) {
            unsigned long long kv = keys[i];
            int j = i - 1;
            while (j >= s0 && keys[j] < kv) { keys[j + 1] = keys[j]; --j; }
            keys[j + 1] = kv;
        }
    }
    __syncthreads();

    // greedy scan (warp 0)
    if (tid < 32 && cnt > 0) {
        int count = 0;
        for (int base = 0; base < cnt && count < MAXB; base += 32) {
            int p = base + lane;
            bool has = (p < cnt);
            unsigned long long key = has ? keys[p] : 0ull;
            unsigned int idx = has ? (0xFFFFFFFFu - (unsigned int)key) : 0u;
            widx[lane] = idx;
            bool sup = has && ((supp[idx >> 5] >> (idx & 31)) & 1u);
            unsigned int pend = __ballot_sync(0xffffffffu, has && !sup);
            __syncwarp(0xffffffffu);
            if (!pend) continue;

            // preload pairwise bits: v bit c = (candidate c suppresses me), c<lane
            unsigned int myw = idx >> 5, myb = idx & 31;
            bool iamp = (pend >> lane) & 1u;
            unsigned int v = 0;
#pragma unroll
            for (int cc = 0; cc < 31; ++cc) {
                bool need = iamp && (cc < lane) && ((pend >> cc) & 1u);
                unsigned int wv = 0;
                if (need) wv = __ldg(&g_mask[(unsigned)widx[cc] * WSTRIDE + myw]);
                v |= ((wv >> myb) & 1u) << cc;
            }

            // register-only greedy within window
            int nk = 0;
            while (pend) {
                int f = __ffs(pend) - 1;
                if (lane == f) {
                    kept[idx >> 5] |= (1u << (idx & 31));
                    klist[nk] = idx;
                }
                ++nk; ++count;
                pend &= ~(1u << f);
                if (count >= MAXB) break;
                unsigned int supbits = __ballot_sync(0xffffffffu, (v >> f) & 1u);
                pend &= ~supbits;
            }
            __syncwarp(0xffffffffu);

            // batch-OR kept rows into supp (independent LDGs across k)
            for (int k = 0; k < nk; ++k) {
                const unsigned int* rowm = &g_mask[(unsigned)klist[k] * WSTRIDE];
#pragma unroll 5
                for (int w = lane; w < WORDS; w += 32)
                    supp[w] |= __ldg(&rowm[w]);
            }
            __syncwarp(0xffffffffu);
        }
    }
    __syncthreads();

    for (int w = tid; w < WSTRIDE; w += BT)
        g_kept[c * WSTRIDE + w] = kept[w];
}

// ---------------------------------------------------------------------------
// Kernel C: assemble output (1,5000,84) = [boxes | kept ? score : 0]
// ---------------------------------------------------------------------------
__global__ void assemble_kernel(const float* __restrict__ boxes,
                                const float* __restrict__ cls,
                                float* __restrict__ out) {
    int t = blockIdx.x * blockDim.x + threadIdx.x;
    if (t >= N_ANCH * OUT_COLS) return;
    int i = t / OUT_COLS;
    int col = t - i * OUT_COLS;
    float v;
    if (col < 4) {
        v = boxes[i * 4 + col];
    } else {
        int cc = col - 4;
        float s = cls[i * N_CLS + cc];
        unsigned int m = g_kept[cc * WSTRIDE + (i >> 5)];
        v = ((m >> (i & 31)) & 1u) ? s : 0.0f;
    }
    out[t] = v;
}

// ---------------------------------------------------------------------------
extern "C" void kernel_launch(void* const* d_in, const int* in_sizes, int n_in,
                              void* d_out, int out_size) {
    const float* boxes = (const float*)d_in[0];   // (1,5000,4)
    const float* cls   = (const float*)d_in[1];   // (1,5000,80)
    float* out = (float*)d_out;                   // (1,5000,84)

    {   // A: 4 rows/warp -> 1250 warps
        int warps = N_ANCH / 4;
        int threads = 256;
        int blocks = (warps * 32 + threads - 1) / threads;
        iou_mask_kernel<<<blocks, threads>>>((const float4*)boxes);
    }
    {   // B
        size_t smem = (size_t)KEYCAP * 8 + (size_t)NBUCK * 4 * 2;  // 73728 B
        static bool attr_set = false;
        if (!attr_set) {
            cudaFuncSetAttribute(nms_class_kernel,
                                 cudaFuncAttributeMaxDynamicSharedMemorySize,
                                 (int)smem);
            attr_set = true;
        }
        nms_class_kernel<<<N_CLS, BT, smem>>>(cls);
    }
    {   // C
        int total = N_ANCH * OUT_COLS;
        assemble_kernel<<<(total + 255) / 256, 256>>>(boxes, cls, out);
    }
}

// round 3
// speedup vs baseline: 2.9850x; 2.9850x over previous
#include <cuda_runtime.h>

#define N_ANCH 5000
#define N_CLS 80
#define WORDS 157          // ceil(5000/32)
#define WSTRIDE 160        // padded row stride (640B)
#define MAXB 300
#define SCORE_THR_F 0.05f
#define OUT_COLS 84
#define NBUCK 4096
#define KEYCAP 5120
#define NTILES ((WORDS * (WORDS + 1)) / 2)   // 12403 upper-triangle 32x32 tiles

// suppression bitmask: bit j of word w of row i <=> iou(i,32w+j)>0.5 && i!=j
__device__ unsigned int g_mask[N_ANCH * WSTRIDE];
__device__ unsigned int g_kept[N_CLS * WSTRIDE];

// ---------------------------------------------------------------------------
// 32x32 bit-matrix transpose across a warp: result lane i bit j = input lane j bit i
// ---------------------------------------------------------------------------
__device__ __forceinline__ unsigned bit_transpose32(unsigned x, int lane) {
    const unsigned lom[5] = {0x0000FFFFu, 0x00FF00FFu, 0x0F0F0F0Fu, 0x33333333u, 0x55555555u};
    const int      shs[5] = {16, 8, 4, 2, 1};
#pragma unroll
    for (int s = 0; s < 5; ++s) {
        unsigned y = __shfl_xor_sync(0xffffffffu, x, shs[s]);
        unsigned lo = lom[s];
        if ((lane & shs[s]) == 0) x = (x & lo)  | ((y & lo)  << shs[s]);
        else                      x = (x & ~lo) | ((y & ~lo) >> shs[s]);
    }
    return x;
}

// ---------------------------------------------------------------------------
// Kernel A: IoU>0.5 bitmask via symmetric 32x32 tiles. Warp per tile (I<=J).
// Exact: fl(inter/uni)>0.5 <=> 2*inter-uni>0 outside a 1e-6 relative band;
// exact __fdiv_rn fallback inside the band (deferred, ~never taken).
// ---------------------------------------------------------------------------
__global__ void __launch_bounds__(256)
iou_tile_kernel(const float4* __restrict__ boxes) {
    __shared__ float4 sbox[8][32];
    __shared__ float  sarea[8][32];

    const int gw   = (blockIdx.x * blockDim.x + threadIdx.x) >> 5;
    const int lane = threadIdx.x & 31;
    const int wib  = (threadIdx.x >> 5);
    if (gw >= NTILES) return;

    // triangular decode: gw = J*(J+1)/2 + I, I <= J
    int J = (int)((sqrtf(8.0f * (float)gw + 1.0f) - 1.0f) * 0.5f);
    while ((J + 1) * (J + 2) / 2 <= gw) ++J;
    while (J * (J + 1) / 2 > gw) --J;
    const int I = gw - J * (J + 1) / 2;

    const int row = (I << 5) + lane;
    const float4 bi = __ldg(&boxes[min(row, N_ANCH - 1)]);
    const float  ai = __fmul_rn(__fsub_rn(bi.z, bi.x), __fsub_rn(bi.w, bi.y));

    const int colL = (J << 5) + lane;
    {
        float4 bc = __ldg(&boxes[min(colL, N_ANCH - 1)]);
        sbox[wib][lane]  = bc;
        sarea[wib][lane] = __fmul_rn(__fsub_rn(bc.z, bc.x), __fsub_rn(bc.w, bc.y));
    }
    __syncwarp(0xffffffffu);

    unsigned word = 0u, fix = 0u;
#pragma unroll
    for (int j = 0; j < 32; ++j) {
        float4 bj = sbox[wib][j];
        float  aj = sarea[wib][j];
        float iw = fmaxf(__fsub_rn(fminf(bi.z, bj.z), fmaxf(bi.x, bj.x)), 0.0f);
        float ih = fmaxf(__fsub_rn(fminf(bi.w, bj.w), fmaxf(bi.y, bj.y)), 0.0f);
        float inter = __fmul_rn(iw, ih);
        float uni   = __fsub_rn(__fadd_rn(ai, aj), inter);      // >= 1 (areas >= 1)
        float diff  = __fmaf_rn(inter, 2.0f, -uni);             // sign-exact off-band
        if (diff > 0.0f)                          word |= (1u << j);
        if (fabsf(diff) <= __fmul_rn(uni, 1e-6f)) fix  |= (1u << j);
    }

    // rare exact-division fixup inside the boundary band
    if (__any_sync(0xffffffffu, fix != 0u)) {
        while (fix) {
            int j = __ffs(fix) - 1; fix &= fix - 1u;
            float4 bj = sbox[wib][j];
            float  aj = sarea[wib][j];
            float iw = fmaxf(__fsub_rn(fminf(bi.z, bj.z), fmaxf(bi.x, bj.x)), 0.0f);
            float ih = fmaxf(__fsub_rn(fminf(bi.w, bj.w), fmaxf(bi.y, bj.y)), 0.0f);
            float inter = __fmul_rn(iw, ih);
            float uni   = __fsub_rn(__fadd_rn(ai, aj), inter);
            float iou   = __fdiv_rn(inter, fmaxf(uni, 1e-8f));
            if (iou > 0.5f) word |=  (1u << j);
            else            word &= ~(1u << j);
        }
    }

    const unsigned cmaskJ = (J == WORDS - 1) ? 0xFFu : 0xFFFFFFFFu;
    const unsigned cmaskI = (I == WORDS - 1) ? 0xFFu : 0xFFFFFFFFu;
    word &= cmaskJ;

    if (I == J) {
        word &= ~(1u << lane);                       // no self-suppression
        if (row < N_ANCH) g_mask[row * WSTRIDE + J] = word;
    } else {
        unsigned t = bit_transpose32(word, lane) & cmaskI;
        g_mask[row * WSTRIDE + J] = word;            // I<J => I<=155 => row<4992+32<=4991? (I<=155 -> row<=4991) always valid
        if (colL < N_ANCH) g_mask[colL * WSTRIDE + I] = t;
    }
}

// ---------------------------------------------------------------------------
// Kernel B: one block (1024 thr) per class.
//   1) counting sort (4096 buckets) + per-bucket insertion sort -> exact
//      stable descending (score_bits<<32 | ~idx) order
//   2) warp-0 greedy scan with depth-4 speculative coalesced row loads
// ---------------------------------------------------------------------------
#define BT 1024

__device__ __forceinline__ unsigned rowbit(const unsigned r[5], unsigned anchor) {
    unsigned wi = anchor >> 5;
    unsigned u  = wi >> 5, hl = wi & 31u;
    unsigned wv = r[0];
    if (u == 1) wv = r[1];
    else if (u == 2) wv = r[2];
    else if (u == 3) wv = r[3];
    else if (u == 4) wv = r[4];
    wv = __shfl_sync(0xffffffffu, wv, hl);
    return (wv >> (anchor & 31u)) & 1u;
}

__global__ void __launch_bounds__(BT, 1)
nms_class_kernel(const float* __restrict__ cls) {
    extern __shared__ unsigned char sh_raw[];
    unsigned long long* keys = (unsigned long long*)sh_raw;      // KEYCAP u64
    unsigned int* hist   = (unsigned int*)(keys + KEYCAP);       // NBUCK
    unsigned int* starts = hist + NBUCK;                         // NBUCK
    __shared__ unsigned int supp[WSTRIDE];
    __shared__ unsigned int kept[WSTRIDE];
    __shared__ unsigned int wsum[32];
    __shared__ int s_cnt;

    const int c = blockIdx.x;
    const int tid = threadIdx.x;
    const int lane = tid & 31;
    const int wid = tid >> 5;

    for (int b = tid; b < NBUCK; b += BT) hist[b] = 0u;
    for (int w = tid; w < WSTRIDE; w += BT) { supp[w] = 0u; kept[w] = 0u; }
    __syncthreads();

    for (int i = tid; i < N_ANCH; i += BT) {
        float s = cls[i * N_CLS + c];
        if (s > SCORE_THR_F) {
            int b = min((int)__fmul_rn(s, 4096.0f), NBUCK - 1);
            atomicAdd(&hist[NBUCK - 1 - b], 1u);
        }
    }
    __syncthreads();

    {   // block exclusive scan, 4 bins/thread
        unsigned h0 = hist[tid * 4 + 0], h1 = hist[tid * 4 + 1];
        unsigned h2 = hist[tid * 4 + 2], h3 = hist[tid * 4 + 3];
        unsigned tsum = h0 + h1 + h2 + h3;
        unsigned x = tsum;
#pragma unroll
        for (int o = 1; o < 32; o <<= 1) {
            unsigned y = __shfl_up_sync(0xffffffffu, x, o);
            if (lane >= o) x += y;
        }
        if (lane == 31) wsum[wid] = x;
        __syncthreads();
        if (wid == 0) {
            unsigned v = wsum[lane], xx = v;
#pragma unroll
            for (int o = 1; o < 32; o <<= 1) {
                unsigned y = __shfl_up_sync(0xffffffffu, xx, o);
                if (lane >= o) xx += y;
            }
            wsum[lane] = xx;
            if (lane == 31) s_cnt = (int)xx;
        }
        __syncthreads();
        unsigned te = ((wid > 0) ? wsum[wid - 1] : 0u) + (x - tsum);
        hist[tid * 4 + 0] = te;                  starts[tid * 4 + 0] = te;
        hist[tid * 4 + 1] = te + h0;             starts[tid * 4 + 1] = te + h0;
        hist[tid * 4 + 2] = te + h0 + h1;        starts[tid * 4 + 2] = te + h0 + h1;
        hist[tid * 4 + 3] = te + h0 + h1 + h2;   starts[tid * 4 + 3] = te + h0 + h1 + h2;
    }
    __syncthreads();
    const int cnt = s_cnt;

    for (int i = tid; i < N_ANCH; i += BT) {
        float s = cls[i * N_CLS + c];
        if (s > SCORE_THR_F) {
            int b = min((int)__fmul_rn(s, 4096.0f), NBUCK - 1);
            unsigned pos = atomicAdd(&hist[NBUCK - 1 - b], 1u);
            keys[pos] = ((unsigned long long)__float_as_uint(s) << 32) |
                        (unsigned long long)(0xFFFFFFFFu - (unsigned)i);
        }
    }
    __syncthreads();

    for (int b = tid; b < NBUCK; b += BT) {
        int s0 = (int)starts[b], e0 = (int)hist[b];
        for (int i = s0 + 1; i < e0; ++i) {
            unsigned long long kv = keys[i];
            int j = i - 1;
            while (j >= s0 && keys[j] < kv) { keys[j + 1] = keys[j]; --j; }
            keys[j + 1] = kv;
        }
    }
    __syncthreads();

    // ---- greedy scan, warp 0, depth-4 speculative row loads ----
    if (tid < 32 && cnt > 0) {
        int count = 0;
        for (int base = 0; base < cnt && count < MAXB; base += 32) {
            int p = base + lane;
            bool has = (p < cnt);
            unsigned long long key = has ? keys[p] : 0ull;
            unsigned idx = has ? (0xFFFFFFFFu - (unsigned)key) : 0u;
            bool sup = has && ((supp[idx >> 5] >> (idx & 31)) & 1u);
            unsigned pend = __ballot_sync(0xffffffffu, has && !sup);

            while (pend && count < MAXB) {
                // first up to 4 alive candidates
                int f[4]; int nf = 0;
                unsigned tmp = pend;
                while (tmp && nf < 4) { f[nf++] = __ffs(tmp) - 1; tmp &= tmp - 1u; }

                unsigned a[4];
                unsigned r[4][5];
#pragma unroll
                for (int k = 0; k < 4; ++k) {
                    if (k < nf) {
                        a[k] = __shfl_sync(0xffffffffu, idx, f[k]);
#pragma unroll
                        for (int u = 0; u < 5; ++u) {
                            int w = lane + (u << 5);
                            r[k][u] = (w < WORDS)
                                ? __ldg(&g_mask[a[k] * WSTRIDE + w]) : 0u;
                        }
                    }
                }

                // resolve keep/suppress in order (uniform across warp)
                bool kb[4] = {false, false, false, false};
                for (int k = 0; k < nf; ++k) {
                    unsigned s = 0u;
                    for (int m = 0; m < k; ++m)
                        if (kb[m]) s |= rowbit(r[m], a[k]);
                    bool keep = (s == 0u);
                    if (keep) {
                        if (count < MAXB) { ++count; kb[k] = true; }
                    }
                }

                if (lane == 0) {
#pragma unroll
                    for (int k = 0; k < 4; ++k)
                        if (k < nf && kb[k])
                            kept[a[k] >> 5] |= (1u << (a[k] & 31u));
                }

#pragma unroll
                for (int k = 0; k < 4; ++k) {
                    if (k < nf && kb[k]) {
#pragma unroll
                        for (int u = 0; u < 5; ++u) {
                            int w = lane + (u << 5);
                            if (w < WORDS) supp[w] |= r[k][u];
                        }
                    }
                }
                __syncwarp(0xffffffffu);

                for (int k = 0; k < nf; ++k) pend &= ~(1u << f[k]);
                bool sup2 = has && ((supp[idx >> 5] >> (idx & 31)) & 1u);
                pend &= __ballot_sync(0xffffffffu, !sup2);
            }
        }
    }
    __syncthreads();

    for (int w = tid; w < WSTRIDE; w += BT)
        g_kept[c * WSTRIDE + w] = kept[w];
}

// ---------------------------------------------------------------------------
// Kernel C: assemble output (1,5000,84) = [boxes | kept ? score : 0]
// ---------------------------------------------------------------------------
__global__ void assemble_kernel(const float* __restrict__ boxes,
                                const float* __restrict__ cls,
                                float* __restrict__ out) {
    int t = blockIdx.x * blockDim.x + threadIdx.x;
    if (t >= N_ANCH * OUT_COLS) return;
    int i = t / OUT_COLS;
    int col = t - i * OUT_COLS;
    float v;
    if (col < 4) {
        v = boxes[i * 4 + col];
    } else {
        int cc = col - 4;
        float s = cls[i * N_CLS + cc];
        unsigned m = g_kept[cc * WSTRIDE + (i >> 5)];
        v = ((m >> (i & 31)) & 1u) ? s : 0.0f;
    }
    out[t] = v;
}

// ---------------------------------------------------------------------------
extern "C" void kernel_launch(void* const* d_in, const int* in_sizes, int n_in,
                              void* d_out, int out_size) {
    const float* boxes = (const float*)d_in[0];   // (1,5000,4)
    const float* cls   = (const float*)d_in[1];   // (1,5000,80)
    float* out = (float*)d_out;                   // (1,5000,84)

    {   // A: warp per upper-triangle tile
        int blocks = (NTILES * 32 + 255) / 256;
        iou_tile_kernel<<<blocks, 256>>>((const float4*)boxes);
    }
    {   // B
        size_t smem = (size_t)KEYCAP * 8 + (size_t)NBUCK * 4 * 2;  // 73728 B
        cudaFuncSetAttribute(nms_class_kernel,
                             cudaFuncAttributeMaxDynamicSharedMemorySize,
                             (int)smem);
        nms_class_kernel<<<N_CLS, BT, smem>>>(cls);
    }
    {   // C
        int total = N_ANCH * OUT_COLS;
        assemble_kernel<<<(total + 255) / 256, 256>>>(boxes, cls, out);
    }
}